// round 16
// baseline (speedup 1.0000x reference)
#include <cuda_runtime.h>
#include <cuda_bf16.h>

// Soft "Until":
//   out[b,t,c] = (1/s) * log( sum_{k=0..kmax} 1/(E_k + exp(-s*psi[t+k])) )
//   E_0 = exp(-s),  E_k = sum_{j<k} exp(-s*phi[t+j]),  kmax = min(63, T-1-t)
//
// Thread = (half h, channel ch, output-pair op): 256 threads/block, NT=128.
// Stream per parity pair: (pe, h=fe+po, g=fe+fo, po) -> ONE LDS.128 per iter.
// Pairwise rcp merge + shared-E const cF=fe(i0) (out0 denoms = out1's + cF).
// Split-k: h=0 covers out1 k'=0..32 / out0 k=0..33; h=1 rebuilds its E prefix
// as a forward sum of g (16 FADD) and covers the rest. Halves combined via
// shared stage. No slow path: pad f=0, p=1e17 (terms contribute ~1e-17).

#define THREADS 256
#define NT      128            // outputs (t positions) per block
#define W       64
#define NE      (NT + W)       // 192
#define NPAIR   (NE / 2)       // 96
#define NPO     (NT / 2)       // 64 output pairs
#define PADP    1e17f

__device__ __forceinline__ float frcp(float x) {
    float r; asm("rcp.approx.f32 %0, %1;" : "=f"(r) : "f"(x)); return r;
}
__device__ __forceinline__ void merge2(float& S, float d1, float d2) {
    S = fmaf(d1 + d2, frcp(d1 * d2), S);
}

__global__ void __launch_bounds__(THREADS, 6) until_kernel(
    const float* __restrict__ phi,
    const float* __restrict__ psi,
    const void* __restrict__ scale_p,
    float* __restrict__ out,
    int T)
{
    __shared__ float4 s_stream[2][NPAIR];  // (pe, h, g, po) per channel
    __shared__ float2 s_raw[2][NPAIR];     // (fe, fo)
    __shared__ float2 s_part[2][2][NPO];   // partial (S0,S1) [h][ch][op]
    __shared__ float2 s_res[2][NPO];       // final (r0,r1) [ch][op]

    // scale dtype heuristic (int32/int64/float32, 1 element)
    int si = *(const int*)scale_p;
    float s = (si > 0 && si < (1 << 20)) ? (float)si : *(const float*)scale_p;
    const float ns = -s;

    const int b   = blockIdx.y;
    const int t0  = blockIdx.x * NT;       // even
    const int tid = threadIdx.x;

    const float4* phi4 = (const float4*)phi + (size_t)b * (T / 2);
    const float4* psi4 = (const float4*)psi + (size_t)b * (T / 2);

    // ---- preamble: one parity pair per thread (tid < NPAIR) ----
    if (tid < NPAIR) {
        int tp = t0 / 2 + tid;
        float fex, fox, pex, pox, fey, foy, pey, poy;
        if (2 * tp < T) {
            float4 ph = phi4[tp];          // (x(2k), y(2k), x(2k+1), y(2k+1))
            float4 ps = psi4[tp];
            fex = __expf(ns * ph.x); fey = __expf(ns * ph.y);
            fox = __expf(ns * ph.z); foy = __expf(ns * ph.w);
            pex = __expf(ns * ps.x); pey = __expf(ns * ps.y);
            pox = __expf(ns * ps.z); poy = __expf(ns * ps.w);
        } else {
            fex = fox = fey = foy = 0.f;
            pex = pox = pey = poy = PADP;
        }
        s_stream[0][tid] = make_float4(pex, fex + pox, fex + fox, pox);
        s_stream[1][tid] = make_float4(pey, fey + poy, fey + foy, poy);
        s_raw[0][tid] = make_float2(fex, fox);
        s_raw[1][tid] = make_float2(fey, foy);
    }
    __syncthreads();

    const int h  = tid >> 7;               // window half
    const int ch = (tid >> 6) & 1;         // 0 = x, 1 = y
    const int op = tid & 63;               // output-pair index

    const float4* Q  = s_stream[ch];
    const float2  R0 = s_raw[ch][op];

    const float E0c   = __expf(ns);
    const float inv_s = frcp(s);
    const float cF    = R0.x;              // fe(i0) = E_out0 - E_out1

    float S0 = 0.f, S1 = 0.f;

    if (h == 0) {
        // ---- lower half: init + iters r = 1..16 ----
        float4 Q0 = Q[op];                 // (pe, h0, g0, po)
        merge2(S0, E0c + Q0.x, Q0.y);      // out0 k=0,1 (cF+po == h0)
        S1 = frcp(E0c + Q0.w);             // out1 lone k'=0
        float Eb = R0.y;                   // fo(i0)

        float4 Qc = Q[op + 1];
        #pragma unroll
        for (int r = 1; r <= 16; ++r) {
            float4 Qn = Q[op + r + 1];     // r=16 prefetch unused (in-bounds)

            float a1 = Eb + Qc.x;          // out1 k'=2r-1
            float b1 = Eb + Qc.y;          // out1 k'=2r
            float u  = a1 + b1;
            float v  = a1 * b1;
            S1 = fmaf(u, frcp(v), S1);

            float w  = u + cF;
            float p0 = fmaf(cF, w, v);     // (a1+cF)(b1+cF)
            float q0 = w + cF;
            S0 = fmaf(q0, frcp(p0), S0);

            Eb += Qc.z;
            Qc = Qn;
        }
    } else {
        // ---- upper half: forward-sum prefix, iters r = 17..31 + tail ----
        float Eb = R0.y;
        #pragma unroll
        for (int r = 1; r <= 16; ++r)
            Eb += Q[op + r].z;             // += fe + fo (all positive)

        float4 Qc = Q[op + 17];
        #pragma unroll
        for (int r = 17; r < 32; ++r) {
            float4 Qn = Q[op + r + 1];     // r=31 prefetches op+32 (tail)

            float a1 = Eb + Qc.x;
            float b1 = Eb + Qc.y;
            float u  = a1 + b1;
            float v  = a1 * b1;
            S1 = fmaf(u, frcp(v), S1);

            float w  = u + cF;
            float p0 = fmaf(cF, w, v);
            float q0 = w + cF;
            S0 = fmaf(q0, frcp(p0), S0);

            Eb += Qc.z;
            Qc = Qn;
        }
        // out1 tail: k'=63 uses pe of pair op+32
        S1 += frcp(Eb + Qc.x);
    }

    s_part[h][ch][op] = make_float2(S0, S1);
    __syncthreads();

    if (h == 0) {
        float2 o = s_part[1][ch][op];
        s_res[ch][op] = make_float2(__logf(S0 + o.x) * inv_s,
                                    __logf(S1 + o.y) * inv_s);
    }
    __syncthreads();

    if (tid < NPO) {
        float2 vx = s_res[0][tid];
        float2 vy = s_res[1][tid];
        float2* out2 = (float2*)out + (size_t)b * T;
        float4 res = make_float4(vx.x, vy.x, vx.y, vy.y);
        *(float4*)(out2 + t0 + 2 * tid) = res;
    }
}

extern "C" void kernel_launch(void* const* d_in, const int* in_sizes, int n_in,
                              void* d_out, int out_size) {
    const float* phi   = (const float*)d_in[0];
    const float* psi   = (const float*)d_in[1];
    const void*  scale = d_in[2];
    float* out = (float*)d_out;

    const int T = 2048;
    const int B = out_size / (T * 2);     // out is [B, T, 2] float32

    dim3 grid(T / NT, B);
    until_kernel<<<grid, THREADS>>>(phi, psi, scale, out, T);
}

// round 17
// speedup vs baseline: 1.2234x; 1.2234x over previous
#include <cuda_runtime.h>
#include <cuda_bf16.h>

// Soft "Until":
//   out[b,t,c] = (1/s) * log( sum_{k=0..kmax} 1/(E_k + exp(-s*psi[t+k])) )
//   E_0 = exp(-s),  E_k = sum_{j<k} exp(-s*phi[t+j]),  kmax = min(63, T-1-t)
//
// One thread = one output pair (t, t+1), BOTH channels, via packed f32x2
// math (add/mul/fma.rn.f32x2). Whole iteration in a single asm block; shared
// streams stored pre-packed (ulonglong2) so LDS.128 feeds packed regs with
// zero marshalling; mov.b64 {lo,hi} around the scalar rcps coalesce to
// register aliasing. Pairwise rcp merge (1/a+1/b=(a+b)*rcp(ab)) + shared-E
// const cF = fe(i0). No slow path: pad f=0, p=1e17 (dead terms).
// 64-thread blocks, grid 1024 -> single resident wave.

#define THREADS 64
#define NT      128            // outputs (t positions) per block
#define W       64
#define NE      (NT + W)       // 192
#define NPAIR   (NE / 2)       // 96
#define PADP    1e17f

typedef unsigned long long u64;

__device__ __forceinline__ float frcp(float x) {
    float r; asm("rcp.approx.f32 %0, %1;" : "=f"(r) : "f"(x)); return r;
}
__device__ __forceinline__ void merge2(float& S, float d1, float d2) {
    S = fmaf(d1 + d2, frcp(d1 * d2), S);
}
__device__ __forceinline__ u64 pk(float lo, float hi) {
    u64 r; asm("mov.b64 %0, {%1, %2};" : "=l"(r) : "f"(lo), "f"(hi)); return r;
}
__device__ __forceinline__ float2 upk(u64 v) {
    float2 t; asm("mov.b64 {%0, %1}, %2;" : "=f"(t.x), "=f"(t.y) : "l"(v)); return t;
}

__global__ void __launch_bounds__(THREADS, 12) until_kernel(
    const float* __restrict__ phi,
    const float* __restrict__ psi,
    const void* __restrict__ scale_p,
    float* __restrict__ out,
    int T)
{
    __shared__ ulonglong2 s_A[NPAIR];      // (pe_pack, h_pack), h = fe+po
    __shared__ u64        s_G[NPAIR];      // g_pack, g = fe+fo
    __shared__ ulonglong2 s_B[NPAIR];      // (po_pack, fo_pack)
    __shared__ u64        s_C[NPAIR];      // fe_pack

    // scale dtype heuristic (int32/int64/float32, 1 element)
    int si = *(const int*)scale_p;
    float s = (si > 0 && si < (1 << 20)) ? (float)si : *(const float*)scale_p;
    const float ns = -s;

    const int b   = blockIdx.y;
    const int t0  = blockIdx.x * NT;       // even
    const int tid = threadIdx.x;

    const float4* phi4 = (const float4*)phi + (size_t)b * (T / 2);
    const float4* psi4 = (const float4*)psi + (size_t)b * (T / 2);

    // ---- preamble: 96 pairs over 64 threads ----
    #pragma unroll
    for (int j = tid; j < NPAIR; j += THREADS) {
        int tp = t0 / 2 + j;
        float fex, fox, pex, pox, fey, foy, pey, poy;
        if (2 * tp < T) {
            float4 ph = phi4[tp];          // (x(2k), y(2k), x(2k+1), y(2k+1))
            float4 ps = psi4[tp];
            fex = __expf(ns * ph.x); fey = __expf(ns * ph.y);
            fox = __expf(ns * ph.z); foy = __expf(ns * ph.w);
            pex = __expf(ns * ps.x); pey = __expf(ns * ps.y);
            pox = __expf(ns * ps.z); poy = __expf(ns * ps.w);
        } else {
            fex = fox = fey = foy = 0.f;
            pex = pox = pey = poy = PADP;
        }
        s_A[j] = make_ulonglong2(pk(pex, pey), pk(fex + pox, fey + poy));
        s_G[j] = pk(fex + fox, fey + foy);
        s_B[j] = make_ulonglong2(pk(pox, poy), pk(fox, foy));
        s_C[j] = pk(fex, fey);
    }
    __syncthreads();

    const int op = tid;                    // output-pair index 0..63
    const float E0c   = __expf(ns);
    const float inv_s = frcp(s);

    // ---- init (scalar; k=0 terms) ----
    float4 A0 = ((const float4*)s_A)[op];  // (pe_x, pe_y, h_x, h_y)
    float4 B0 = ((const float4*)s_B)[op];  // (po_x, po_y, fo_x, fo_y)
    float2 C0 = ((const float2*)s_C)[op];  // (fe_x, fe_y)

    float S0x = 0.f, S0y = 0.f;
    merge2(S0x, E0c + A0.x, A0.z);         // out0 k=0,1 (cF+po == h)
    merge2(S0y, E0c + A0.y, A0.w);
    float S1x = frcp(E0c + B0.x);          // out1 lone k'=0
    float S1y = frcp(E0c + B0.y);

    u64 S0 = pk(S0x, S0y);
    u64 S1 = pk(S1x, S1y);
    u64 Eb = pk(B0.z, B0.w);               // fo(i0)
    u64 CF = pk(C0.x, C0.y);               // fe(i0) = E_out0 - E_out1

    // ---- main loop: 31 packed iterations, 4 terms x 2 channels each ----
    #pragma unroll
    for (int r = 1; r < 32; ++r) {
        ulonglong2 Ac = s_A[op + r];       // LDS.128 -> (pe_pack, h_pack)
        u64 g = s_G[op + r];               // LDS.64

        asm("{\n\t"
            ".reg .b64 a, b, u, v, w, p, q, rv, rp;\n\t"
            ".reg .f32 lo, hi, r0, r1;\n\t"
            "add.rn.f32x2 a, %2, %3;\n\t"      // a1 = Eb + pe
            "add.rn.f32x2 b, %2, %4;\n\t"      // b1 = Eb + h
            "add.rn.f32x2 u, a, b;\n\t"
            "mul.rn.f32x2 v, a, b;\n\t"
            "mov.b64 {lo, hi}, v;\n\t"
            "rcp.approx.f32 r0, lo;\n\t"
            "rcp.approx.f32 r1, hi;\n\t"
            "mov.b64 rv, {r0, r1};\n\t"
            "fma.rn.f32x2 %1, u, rv, %1;\n\t"  // S1 += u * rcp(v)
            "add.rn.f32x2 w, u, %5;\n\t"       // w = u + cF
            "fma.rn.f32x2 p, %5, w, v;\n\t"    // p0 = (a1+cF)(b1+cF)
            "add.rn.f32x2 q, w, %5;\n\t"       // q0 = sum0
            "mov.b64 {lo, hi}, p;\n\t"
            "rcp.approx.f32 r0, lo;\n\t"
            "rcp.approx.f32 r1, hi;\n\t"
            "mov.b64 rp, {r0, r1};\n\t"
            "fma.rn.f32x2 %0, q, rp, %0;\n\t"  // S0 += q0 * rcp(p0)
            "add.rn.f32x2 %2, %2, %6;\n\t"     // Eb += g
            "}"
            : "+l"(S0), "+l"(S1), "+l"(Eb)
            : "l"(Ac.x), "l"(Ac.y), "l"(CF), "l"(g));
    }

    // ---- tail: out1 k'=63 uses pe of pair op+32 ----
    float4 At = ((const float4*)s_A)[op + 32];
    float2 ebf = upk(Eb);
    float2 s0f = upk(S0);
    float2 s1f = upk(S1);
    s1f.x += frcp(ebf.x + At.x);
    s1f.y += frcp(ebf.y + At.y);

    // ---- epilogue: direct STG.128 (out0.x, out0.y, out1.x, out1.y) ----
    float2* out2 = (float2*)out + (size_t)b * T;
    float4 res;
    res.x = __logf(s0f.x) * inv_s;
    res.y = __logf(s0f.y) * inv_s;
    res.z = __logf(s1f.x) * inv_s;
    res.w = __logf(s1f.y) * inv_s;
    *(float4*)(out2 + t0 + 2 * op) = res;
}

extern "C" void kernel_launch(void* const* d_in, const int* in_sizes, int n_in,
                              void* d_out, int out_size) {
    const float* phi   = (const float*)d_in[0];
    const float* psi   = (const float*)d_in[1];
    const void*  scale = d_in[2];
    float* out = (float*)d_out;

    const int T = 2048;
    const int B = out_size / (T * 2);     // out is [B, T, 2] float32

    dim3 grid(T / NT, B);
    until_kernel<<<grid, THREADS>>>(phi, psi, scale, out, T);
}